// round 4
// baseline (speedup 1.0000x reference)
#include <cuda_runtime.h>
#include <cstdint>
#include <cstddef>

#define H_DIM 128
#define TILE_N 64
#define BK 32
#define MAX_E 1048576
#define MAX_NODES 100480
#define MAX_SIDE 51200
#define PSTRIDE 12
#define MAX_C 12
#define SCAN_B 256
#define MAX_SCAN_BLK 512

// ---------------- device scratch (no allocations allowed) ----------------
__device__ __align__(16) float g_x  [(size_t)MAX_NODES * H_DIM];
__device__ __align__(16) float g_hs [(size_t)MAX_NODES * H_DIM];
__device__ int   g_deg   [MAX_NODES];
__device__ int   g_off   [MAX_NODES];
__device__ int   g_cursor[MAX_NODES];
__device__ float g_dinv  [MAX_NODES];
__device__ int   g_row[MAX_E];
__device__ int   g_col[MAX_E];
__device__ int   g_csr[MAX_E];            // source node per bucketed edge
__device__ int   g_bsum [MAX_SCAN_BLK];
__device__ int   g_bsum2[MAX_SCAN_BLK];
__device__ float g_pu[(size_t)MAX_SIDE * PSTRIDE];
__device__ float g_pm[(size_t)MAX_SIDE * PSTRIDE];
__device__ int   g_is64;

// packed f32x2 FMA: d = a*b + d  (FFMA2 — only reachable via explicit PTX)
__device__ __forceinline__ void ffma2(unsigned long long& d,
                                      unsigned long long a,
                                      unsigned long long b)
{
    asm("fma.rn.f32x2 %0, %1, %2, %3;" : "=l"(d) : "l"(a), "l"(b), "l"(d));
}

// ---------------- detect edge dtype + zero degree array (fused) ----------------
// If the buffer is really int32 [2E], reading as int64 fuses pairs; since all
// valid ids < 50000, a genuine int64 buffer has every value in [0, 2^32).
__global__ void mp_detect_zero_kernel(const void* ei, int N)
{
    int i = blockIdx.x * blockDim.x + threadIdx.x;
    if (i < N) g_deg[i] = 0;
    if (i == 0) {
        const long long* p = (const long long*)ei;
        int is64 = 1;
        #pragma unroll 1
        for (int k = 0; k < 32; k++) {
            long long v = p[k];
            if (v < 0 || v >= (1LL << 32)) { is64 = 0; break; }
        }
        g_is64 = is64;
    }
}

// ---------------- convert edges to int32 + count in-degree (fused) ----------------
__global__ void mp_convert_kernel(const void* ei, int E)
{
    int e = blockIdx.x * blockDim.x + threadIdx.x;
    if (e >= E) return;
    int r, c;
    if (g_is64) {
        const long long* p = (const long long*)ei;
        r = (int)p[e];
        c = (int)p[(size_t)E + e];
    } else {
        const int* p = (const int*)ei;
        r = p[e];
        c = p[E + e];
    }
    g_row[e] = r;
    g_col[e] = c;
    atomicAdd(&g_deg[c], 1);
}

// ---------------- 3-phase exclusive scan over g_deg -> g_off ----------------
__global__ void mp_scan1_kernel(int N)
{
    __shared__ int sh[SCAN_B];
    int t = threadIdx.x;
    int i = blockIdx.x * SCAN_B + t;
    int v = (i < N) ? g_deg[i] : 0;
    sh[t] = v;
    __syncthreads();
    #pragma unroll
    for (int ofs = 1; ofs < SCAN_B; ofs <<= 1) {
        int u = (t >= ofs) ? sh[t - ofs] : 0;
        __syncthreads();
        sh[t] += u;
        __syncthreads();
    }
    if (i < N) g_off[i] = sh[t] - v;                 // exclusive within block
    if (t == SCAN_B - 1) g_bsum[blockIdx.x] = sh[t]; // block total
}

__global__ void mp_scan2_kernel(int nb)
{
    __shared__ int sh[MAX_SCAN_BLK];
    int t = threadIdx.x;
    int v = (t < nb) ? g_bsum[t] : 0;
    sh[t] = v;
    __syncthreads();
    #pragma unroll
    for (int ofs = 1; ofs < MAX_SCAN_BLK; ofs <<= 1) {
        int u = (t >= ofs) ? sh[t - ofs] : 0;
        __syncthreads();
        sh[t] += u;
        __syncthreads();
    }
    if (t < nb) g_bsum2[t] = sh[t] - v;              // exclusive block offsets
}

// add block offsets, init cursors, compute dinv (deg + self-loop)
__global__ void mp_scan3_kernel(int N)
{
    int i = blockIdx.x * blockDim.x + threadIdx.x;
    if (i >= N) return;
    int off = g_off[i] + g_bsum2[i >> 8];            // SCAN_B == 256
    g_off[i] = off;
    g_cursor[i] = off;
    g_dinv[i] = rsqrtf((float)(g_deg[i] + 1));
}

// ---------------- bucket fill: csr[pos] = row, bucketed by col ----------------
__global__ void mp_fill_kernel(int E)
{
    int e = blockIdx.x * blockDim.x + threadIdx.x;
    if (e >= E) return;
    int pos = atomicAdd(&g_cursor[g_col[e]], 1);
    g_csr[pos] = g_row[e];
}

// ---------------- node linear body: Y = (X @ W^T + b) [* dinv] ----------------
// Tile: 64 nodes x 128 outs per block, 256 threads, each thread 4x8 microtile.
// Inner loop uses packed f32x2 FMA (adjacent output channels paired).
template<int K, bool SCALE>
__device__ __forceinline__ void mp_linear_body(const float* __restrict__ X, int N,
                                               const float* __restrict__ W,
                                               const float* __restrict__ B,
                                               float* __restrict__ Y0,
                                               int bid, int dinv_ofs)
{
    __shared__ __align__(16) float  Ws[BK][H_DIM];      // transposed chunk [k][o]
    __shared__ __align__(16) float2 Xs[TILE_N][BK + 1]; // duplicated (v,v) pairs

    const int tid = threadIdx.x;
    const int tx = tid & 15;    // out-group (8 outs = 4 f32x2 pairs)
    const int ty = tid >> 4;    // node-group (4 nodes)
    const int node0 = bid * TILE_N;

    unsigned long long acc[4][4];
    #pragma unroll
    for (int i = 0; i < 4; i++)
        #pragma unroll
        for (int j = 0; j < 4; j++) acc[i][j] = 0ull;

    #pragma unroll 1
    for (int kc = 0; kc < K; kc += BK) {
        // W chunk: H_DIM x BK floats = 1024 float4, 4 per thread
        #pragma unroll
        for (int j = 0; j < (H_DIM * BK / 4) / 256; j++) {
            int f = tid + j * 256;
            int o = f >> 3;
            int q = f & 7;
            float4 v = *reinterpret_cast<const float4*>(W + (size_t)o * K + kc + q * 4);
            Ws[q * 4 + 0][o] = v.x;
            Ws[q * 4 + 1][o] = v.y;
            Ws[q * 4 + 2][o] = v.z;
            Ws[q * 4 + 3][o] = v.w;
        }
        // X tile: TILE_N x BK = 512 float4, 2 per thread; store duplicated pairs
        #pragma unroll
        for (int j = 0; j < (TILE_N * BK / 4) / 256; j++) {
            int f = tid + j * 256;
            int n = f >> 3;
            int q = f & 7;
            int node = node0 + n;
            if (node >= N) node = N - 1;           // clamped (stores guarded)
            float4 v = *reinterpret_cast<const float4*>(X + (size_t)node * K + kc + q * 4);
            Xs[n][q * 4 + 0] = make_float2(v.x, v.x);
            Xs[n][q * 4 + 1] = make_float2(v.y, v.y);
            Xs[n][q * 4 + 2] = make_float2(v.z, v.z);
            Xs[n][q * 4 + 3] = make_float2(v.w, v.w);
        }
        __syncthreads();

        #pragma unroll 8
        for (int kk = 0; kk < BK; kk++) {
            const unsigned long long* wp =
                reinterpret_cast<const unsigned long long*>(&Ws[kk][0]);
            unsigned long long w0 = wp[tx * 4 + 0];
            unsigned long long w1 = wp[tx * 4 + 1];
            unsigned long long w2 = wp[tx * 4 + 2];
            unsigned long long w3 = wp[tx * 4 + 3];
            #pragma unroll
            for (int i = 0; i < 4; i++) {
                unsigned long long xv =
                    *reinterpret_cast<const unsigned long long*>(&Xs[ty * 4 + i][kk]);
                ffma2(acc[i][0], xv, w0);
                ffma2(acc[i][1], xv, w1);
                ffma2(acc[i][2], xv, w2);
                ffma2(acc[i][3], xv, w3);
            }
        }
        __syncthreads();
    }

    float breg[8];
    #pragma unroll
    for (int j = 0; j < 8; j++) breg[j] = B[tx * 8 + j];

    #pragma unroll
    for (int i = 0; i < 4; i++) {
        int node = node0 + ty * 4 + i;
        if (node >= N) continue;
        float s = SCALE ? g_dinv[node + dinv_ofs] : 1.f;
        float r[8];
        #pragma unroll
        for (int j = 0; j < 4; j++) {
            float2 p = *reinterpret_cast<float2*>(&acc[i][j]);
            r[2 * j + 0] = (p.x + breg[2 * j + 0]) * s;
            r[2 * j + 1] = (p.y + breg[2 * j + 1]) * s;
        }
        float* dst0 = Y0 + (size_t)node * H_DIM + tx * 8;
        *reinterpret_cast<float4*>(dst0)     = make_float4(r[0], r[1], r[2], r[3]);
        *reinterpret_cast<float4*>(dst0 + 4) = make_float4(r[4], r[5], r[6], r[7]);
    }
}

template<int K, bool SCALE>
__global__ void mp_linear_kernel(const float* __restrict__ X, int N,
                                 const float* __restrict__ W,
                                 const float* __restrict__ B,
                                 float* __restrict__ Y0)
{
    mp_linear_body<K, SCALE>(X, N, W, B, Y0, blockIdx.x, 0);
}

// Both input feature transforms in one launch: blocks [0,gU) user, rest movie.
template<int KU, int KM>
__global__ void mp_transform_kernel(const float* __restrict__ Xu, int Nu,
                                    const float* __restrict__ Wu,
                                    const float* __restrict__ Bu,
                                    const float* __restrict__ Xm, int Nm,
                                    const float* __restrict__ Wm,
                                    const float* __restrict__ Bm,
                                    float* __restrict__ Y, int gU)
{
    if ((int)blockIdx.x < gU)
        mp_linear_body<KU, false>(Xu, Nu, Wu, Bu, Y, blockIdx.x, 0);
    else
        mp_linear_body<KM, false>(Xm, Nm, Wm, Bm, Y + (size_t)Nu * H_DIM,
                                  blockIdx.x - gU, 0);
}

// ---------------- aggregate layer1: x[n] = relu(dinv[n]*(hs[n] + sum hs[src])) --------
// One warp per destination node. Neighbor ids loaded cooperatively (one LDG
// per lane, shfl-broadcast) so the 512B row gathers overlap (MLP ~ degree).
__device__ __forceinline__ float4 mp_agg_core(int n, int lane)
{
    const float4* hsp = reinterpret_cast<const float4*>(g_hs);
    float4 acc = __ldg(hsp + (size_t)n * (H_DIM / 4) + lane);   // self-loop

    int beg = g_off[n];
    int end = beg + g_deg[n];
    for (int base = beg; base < end; base += 32) {
        int m = end - base;
        if (m > 32) m = 32;
        int idx = (lane < m) ? g_csr[base + lane] : 0;
        #pragma unroll 4
        for (int j = 0; j < m; j++) {
            int r = __shfl_sync(0xffffffffu, idx, j);
            float4 v = __ldg(hsp + (size_t)r * (H_DIM / 4) + lane);
            acc.x += v.x; acc.y += v.y; acc.z += v.z; acc.w += v.w;
        }
    }

    float s = g_dinv[n];
    acc.x = fmaxf(acc.x * s, 0.f);
    acc.y = fmaxf(acc.y * s, 0.f);
    acc.z = fmaxf(acc.z * s, 0.f);
    acc.w = fmaxf(acc.w * s, 0.f);
    return acc;
}

__global__ void mp_aggregate_kernel(int N)
{
    int id = blockIdx.x * blockDim.x + threadIdx.x;
    int n = id >> 5;
    if (n >= N) return;
    int lane = id & 31;
    float4 acc = mp_agg_core(n, lane);
    reinterpret_cast<float4*>(g_x)[(size_t)n * (H_DIM / 4) + lane] = acc;
}

// ---------------- fused layer-2 aggregate + edge-head projection ----------------
// Same aggregation, but instead of storing x, immediately project to C dims:
// user  n:  pu[n]    = x . WeU + be
// movie n:  pm[n-Nu] = x . WeM
__global__ void mp_agg_proj_kernel(const float* __restrict__ We,
                                   const float* __restrict__ be,
                                   int Nu, int N, int C)
{
    __shared__ float WeS[MAX_C][2 * H_DIM];
    __shared__ float beS[MAX_C];
    {
        int tid = threadIdx.x;
        for (int i = tid; i < C * 2 * H_DIM; i += blockDim.x)
            WeS[i / (2 * H_DIM)][i % (2 * H_DIM)] = We[i];
        if (tid < C) beS[tid] = be[tid];
        __syncthreads();
    }

    int id = blockIdx.x * blockDim.x + threadIdx.x;
    int n = id >> 5;
    if (n >= N) return;
    int lane = id & 31;
    float4 acc = mp_agg_core(n, lane);

    bool isU = n < Nu;
    int k = (isU ? 0 : H_DIM) + lane * 4;

    float p[MAX_C];
    #pragma unroll
    for (int c = 0; c < MAX_C; c++) {
        if (c < C) {
            p[c] = acc.x * WeS[c][k + 0] + acc.y * WeS[c][k + 1]
                 + acc.z * WeS[c][k + 2] + acc.w * WeS[c][k + 3];
        } else p[c] = 0.f;
    }
    // warp butterfly reduce all C partial dots
    #pragma unroll
    for (int ofs = 16; ofs > 0; ofs >>= 1) {
        #pragma unroll
        for (int c = 0; c < MAX_C; c++)
            p[c] += __shfl_down_sync(0xffffffffu, p[c], ofs);
    }
    if (lane == 0) {
        float* dst = isU ? (g_pu + (size_t)n * PSTRIDE)
                         : (g_pm + (size_t)(n - Nu) * PSTRIDE);
        for (int c = 0; c < C; c++)
            dst[c] = p[c] + (isU ? beS[c] : 0.f);
    }
}

// ---------------- out[e] = pu[row[e]] + pm[col[e]] ----------------
__global__ void mp_edge_out_kernel(float* __restrict__ out, int E, int C)
{
    int e = blockIdx.x * blockDim.x + threadIdx.x;
    if (e >= E) return;
    int r = g_row[e];
    int c = g_col[e];
    const float* a = g_pu + (size_t)r * PSTRIDE;
    const float* b = g_pm + (size_t)c * PSTRIDE;
    float* o = out + (size_t)e * C;
    if ((C & 1) == 0) {
        for (int k = 0; k < C; k += 2) {
            float2 av = *reinterpret_cast<const float2*>(a + k);
            float2 bv = *reinterpret_cast<const float2*>(b + k);
            float2 ov;
            ov.x = av.x + bv.x;
            ov.y = av.y + bv.y;
            *reinterpret_cast<float2*>(o + k) = ov;
        }
    } else {
        for (int k = 0; k < C; k++) o[k] = a[k] + b[k];
    }
}

// ---------------- host launch ----------------
extern "C" void kernel_launch(void* const* d_in, const int* in_sizes, int n_in,
                              void* d_out, int out_size)
{
    const float* x_user  = (const float*)d_in[0];
    const float* x_movie = (const float*)d_in[1];
    const void*  eidx    = d_in[2];
    const float* Wu = (const float*)d_in[3];
    const float* bu = (const float*)d_in[4];
    const float* Wm = (const float*)d_in[5];
    const float* bm = (const float*)d_in[6];
    const float* W1 = (const float*)d_in[7];
    const float* b1 = (const float*)d_in[8];
    const float* W2 = (const float*)d_in[9];
    const float* b2 = (const float*)d_in[10];
    const float* We = (const float*)d_in[11];
    const float* be = (const float*)d_in[12];
    float* out = (float*)d_out;

    const int H  = in_sizes[4];
    const int Fu = in_sizes[3] / H;
    const int Fm = in_sizes[5] / H;
    const int Nu = in_sizes[0] / Fu;
    const int Nm = in_sizes[1] / Fm;
    int E        = in_sizes[2] / 2;
    const int C  = in_sizes[12];
    const int Ntot = Nu + Nm;
    if (E > MAX_E) E = MAX_E;

    float* xp;  cudaGetSymbolAddress((void**)&xp,  g_x);
    float* hsp; cudaGetSymbolAddress((void**)&hsp, g_hs);

    const int nb = (Ntot + SCAN_B - 1) / SCAN_B;

    mp_detect_zero_kernel<<<(Ntot + 255) / 256, 256>>>(eidx, Ntot);
    mp_convert_kernel<<<(E + 255) / 256, 256>>>(eidx, E);
    mp_scan1_kernel<<<nb, SCAN_B>>>(Ntot);
    mp_scan2_kernel<<<1, MAX_SCAN_BLK>>>(nb);
    mp_scan3_kernel<<<(Ntot + 255) / 256, 256>>>(Ntot);
    mp_fill_kernel<<<(E + 255) / 256, 256>>>(E);

    // Input feature transforms into g_x (single launch when shapes match)
    int gU = (Nu + TILE_N - 1) / TILE_N;
    int gM = (Nm + TILE_N - 1) / TILE_N;
    if (Fu == 32 && Fm == 64) {
        mp_transform_kernel<32, 64><<<gU + gM, 256>>>(
            x_user, Nu, Wu, bu, x_movie, Nm, Wm, bm, xp, gU);
    } else {
        if (Fu == 32)       mp_linear_kernel< 32, false><<<gU, 256>>>(x_user, Nu, Wu, bu, xp);
        else if (Fu == 64)  mp_linear_kernel< 64, false><<<gU, 256>>>(x_user, Nu, Wu, bu, xp);
        else                mp_linear_kernel<128, false><<<gU, 256>>>(x_user, Nu, Wu, bu, xp);
        float* dst = xp + (size_t)Nu * H_DIM;
        if (Fm == 32)       mp_linear_kernel< 32, false><<<gM, 256>>>(x_movie, Nm, Wm, bm, dst);
        else if (Fm == 64)  mp_linear_kernel< 64, false><<<gM, 256>>>(x_movie, Nm, Wm, bm, dst);
        else                mp_linear_kernel<128, false><<<gM, 256>>>(x_movie, Nm, Wm, bm, dst);
    }

    int gN = (Ntot + TILE_N - 1) / TILE_N;
    int gA = (int)(((long long)Ntot * 32 + 255) / 256);

    // GNN layer 1
    mp_linear_kernel<128, true><<<gN, 256>>>(xp, Ntot, W1, b1, hsp);
    mp_aggregate_kernel<<<gA, 256>>>(Ntot);

    // GNN layer 2 (aggregate fused with edge-head projection)
    mp_linear_kernel<128, true><<<gN, 256>>>(xp, Ntot, W2, b2, hsp);
    mp_agg_proj_kernel<<<gA, 256>>>(We, be, Nu, Ntot, C);

    // Per-edge output: gather + add
    mp_edge_out_kernel<<<(E + 255) / 256, 256>>>(out, E, C);
}

// round 5
// speedup vs baseline: 1.0974x; 1.0974x over previous
#include <cuda_runtime.h>
#include <cuda_fp16.h>
#include <cstdint>
#include <cstddef>

#define H_DIM 128
#define TILE_N 64
#define BK 32
#define MAX_E 1048576
#define MAX_NODES 100480
#define MAX_SIDE 51200
#define PSTRIDE 12
#define MAX_C 12
#define SCAN_B 256
#define MAX_SCAN_BLK 512

// ---------------- device scratch (no allocations allowed) ----------------
__device__ __align__(16) float  g_x  [(size_t)MAX_NODES * H_DIM];
__device__ __align__(16) __half g_hsh[(size_t)MAX_NODES * H_DIM];  // fp16 hs
__device__ int   g_deg   [MAX_NODES];
__device__ int   g_off   [MAX_NODES];
__device__ int   g_cursor[MAX_NODES];
__device__ float g_dinv  [MAX_NODES];
__device__ int   g_row[MAX_E];
__device__ int   g_col[MAX_E];
__device__ int   g_csr[MAX_E];            // source node per bucketed edge
__device__ int   g_bsum [MAX_SCAN_BLK];
__device__ int   g_bsum2[MAX_SCAN_BLK];
__device__ float g_pu[(size_t)MAX_SIDE * PSTRIDE];
__device__ float g_pm[(size_t)MAX_SIDE * PSTRIDE];
__device__ int   g_is64;

// packed f32x2 FMA: d = a*b + d  (FFMA2 — only reachable via explicit PTX)
__device__ __forceinline__ void ffma2(unsigned long long& d,
                                      unsigned long long a,
                                      unsigned long long b)
{
    asm("fma.rn.f32x2 %0, %1, %2, %3;" : "=l"(d) : "l"(a), "l"(b), "l"(d));
}

// ---------------- detect edge dtype + zero degree array (fused) ----------------
// If the buffer is really int32 [2E], reading as int64 fuses pairs; since all
// valid ids < 50000, a genuine int64 buffer has every value in [0, 2^32).
__global__ void mp_detect_zero_kernel(const void* ei, int N)
{
    int i = blockIdx.x * blockDim.x + threadIdx.x;
    if (i < N) g_deg[i] = 0;
    if (i == 0) {
        const long long* p = (const long long*)ei;
        int is64 = 1;
        #pragma unroll 1
        for (int k = 0; k < 32; k++) {
            long long v = p[k];
            if (v < 0 || v >= (1LL << 32)) { is64 = 0; break; }
        }
        g_is64 = is64;
    }
}

// ---------------- convert edges to int32 + count in-degree (fused) ----------------
__global__ void mp_convert_kernel(const void* ei, int E)
{
    int e = blockIdx.x * blockDim.x + threadIdx.x;
    if (e >= E) return;
    int r, c;
    if (g_is64) {
        const long long* p = (const long long*)ei;
        r = (int)p[e];
        c = (int)p[(size_t)E + e];
    } else {
        const int* p = (const int*)ei;
        r = p[e];
        c = p[E + e];
    }
    g_row[e] = r;
    g_col[e] = c;
    atomicAdd(&g_deg[c], 1);
}

// ---------------- 3-phase exclusive scan over g_deg -> g_off ----------------
__global__ void mp_scan1_kernel(int N)
{
    __shared__ int sh[SCAN_B];
    int t = threadIdx.x;
    int i = blockIdx.x * SCAN_B + t;
    int v = (i < N) ? g_deg[i] : 0;
    sh[t] = v;
    __syncthreads();
    #pragma unroll
    for (int ofs = 1; ofs < SCAN_B; ofs <<= 1) {
        int u = (t >= ofs) ? sh[t - ofs] : 0;
        __syncthreads();
        sh[t] += u;
        __syncthreads();
    }
    if (i < N) g_off[i] = sh[t] - v;                 // exclusive within block
    if (t == SCAN_B - 1) g_bsum[blockIdx.x] = sh[t]; // block total
}

__global__ void mp_scan2_kernel(int nb)
{
    __shared__ int sh[MAX_SCAN_BLK];
    int t = threadIdx.x;
    int v = (t < nb) ? g_bsum[t] : 0;
    sh[t] = v;
    __syncthreads();
    #pragma unroll
    for (int ofs = 1; ofs < MAX_SCAN_BLK; ofs <<= 1) {
        int u = (t >= ofs) ? sh[t - ofs] : 0;
        __syncthreads();
        sh[t] += u;
        __syncthreads();
    }
    if (t < nb) g_bsum2[t] = sh[t] - v;              // exclusive block offsets
}

// add block offsets, init cursors, compute dinv (deg + self-loop)
__global__ void mp_scan3_kernel(int N)
{
    int i = blockIdx.x * blockDim.x + threadIdx.x;
    if (i >= N) return;
    int off = g_off[i] + g_bsum2[i >> 8];            // SCAN_B == 256
    g_off[i] = off;
    g_cursor[i] = off;
    g_dinv[i] = rsqrtf((float)(g_deg[i] + 1));
}

// ---------------- bucket fill: csr[pos] = row, bucketed by col ----------------
__global__ void mp_fill_kernel(int E)
{
    int e = blockIdx.x * blockDim.x + threadIdx.x;
    if (e >= E) return;
    int pos = atomicAdd(&g_cursor[g_col[e]], 1);
    g_csr[pos] = g_row[e];
}

// ---------------- node linear body: Y = (X @ W^T + b) [* dinv] ----------------
// Tile: 64 nodes x 128 outs per block, 256 threads, each thread 4x8 microtile.
// Inner loop uses packed f32x2 FMA (adjacent output channels paired).
// HOUT: write fp16 (to g_hsh) instead of fp32.
template<int K, bool SCALE, bool HOUT>
__device__ __forceinline__ void mp_linear_body(const float* __restrict__ X, int N,
                                               const float* __restrict__ W,
                                               const float* __restrict__ B,
                                               float* __restrict__ Yf,
                                               __half* __restrict__ Yh,
                                               int bid)
{
    __shared__ __align__(16) float  Ws[BK][H_DIM];      // transposed chunk [k][o]
    __shared__ __align__(16) float2 Xs[TILE_N][BK + 1]; // duplicated (v,v) pairs

    const int tid = threadIdx.x;
    const int tx = tid & 15;    // out-group (8 outs = 4 f32x2 pairs)
    const int ty = tid >> 4;    // node-group (4 nodes)
    const int node0 = bid * TILE_N;

    unsigned long long acc[4][4];
    #pragma unroll
    for (int i = 0; i < 4; i++)
        #pragma unroll
        for (int j = 0; j < 4; j++) acc[i][j] = 0ull;

    #pragma unroll 1
    for (int kc = 0; kc < K; kc += BK) {
        // W chunk: H_DIM x BK floats = 1024 float4, 4 per thread
        #pragma unroll
        for (int j = 0; j < (H_DIM * BK / 4) / 256; j++) {
            int f = tid + j * 256;
            int o = f >> 3;
            int q = f & 7;
            float4 v = *reinterpret_cast<const float4*>(W + (size_t)o * K + kc + q * 4);
            Ws[q * 4 + 0][o] = v.x;
            Ws[q * 4 + 1][o] = v.y;
            Ws[q * 4 + 2][o] = v.z;
            Ws[q * 4 + 3][o] = v.w;
        }
        // X tile: TILE_N x BK = 512 float4, 2 per thread; store duplicated pairs
        #pragma unroll
        for (int j = 0; j < (TILE_N * BK / 4) / 256; j++) {
            int f = tid + j * 256;
            int n = f >> 3;
            int q = f & 7;
            int node = node0 + n;
            if (node >= N) node = N - 1;           // clamped (stores guarded)
            float4 v = *reinterpret_cast<const float4*>(X + (size_t)node * K + kc + q * 4);
            Xs[n][q * 4 + 0] = make_float2(v.x, v.x);
            Xs[n][q * 4 + 1] = make_float2(v.y, v.y);
            Xs[n][q * 4 + 2] = make_float2(v.z, v.z);
            Xs[n][q * 4 + 3] = make_float2(v.w, v.w);
        }
        __syncthreads();

        #pragma unroll 8
        for (int kk = 0; kk < BK; kk++) {
            const unsigned long long* wp =
                reinterpret_cast<const unsigned long long*>(&Ws[kk][0]);
            unsigned long long w0 = wp[tx * 4 + 0];
            unsigned long long w1 = wp[tx * 4 + 1];
            unsigned long long w2 = wp[tx * 4 + 2];
            unsigned long long w3 = wp[tx * 4 + 3];
            #pragma unroll
            for (int i = 0; i < 4; i++) {
                unsigned long long xv =
                    *reinterpret_cast<const unsigned long long*>(&Xs[ty * 4 + i][kk]);
                ffma2(acc[i][0], xv, w0);
                ffma2(acc[i][1], xv, w1);
                ffma2(acc[i][2], xv, w2);
                ffma2(acc[i][3], xv, w3);
            }
        }
        __syncthreads();
    }

    float breg[8];
    #pragma unroll
    for (int j = 0; j < 8; j++) breg[j] = B[tx * 8 + j];

    #pragma unroll
    for (int i = 0; i < 4; i++) {
        int node = node0 + ty * 4 + i;
        if (node >= N) continue;
        float s = SCALE ? g_dinv[node] : 1.f;
        float r[8];
        #pragma unroll
        for (int j = 0; j < 4; j++) {
            float2 p = *reinterpret_cast<float2*>(&acc[i][j]);
            r[2 * j + 0] = (p.x + breg[2 * j + 0]) * s;
            r[2 * j + 1] = (p.y + breg[2 * j + 1]) * s;
        }
        if (HOUT) {
            __half2 h[4];
            #pragma unroll
            for (int j = 0; j < 4; j++)
                h[j] = __floats2half2_rn(r[2 * j], r[2 * j + 1]);
            *reinterpret_cast<uint4*>(Yh + (size_t)node * H_DIM + tx * 8) =
                *reinterpret_cast<const uint4*>(h);
        } else {
            float* dst0 = Yf + (size_t)node * H_DIM + tx * 8;
            *reinterpret_cast<float4*>(dst0)     = make_float4(r[0], r[1], r[2], r[3]);
            *reinterpret_cast<float4*>(dst0 + 4) = make_float4(r[4], r[5], r[6], r[7]);
        }
    }
}

template<int K>
__global__ void mp_linear_h_kernel(const float* __restrict__ X, int N,
                                   const float* __restrict__ W,
                                   const float* __restrict__ B,
                                   __half* __restrict__ Yh)
{
    mp_linear_body<K, true, true>(X, N, W, B, nullptr, Yh, blockIdx.x);
}

template<int K>
__global__ void mp_linear_f_kernel(const float* __restrict__ X, int N,
                                   const float* __restrict__ W,
                                   const float* __restrict__ B,
                                   float* __restrict__ Yf)
{
    mp_linear_body<K, false, false>(X, N, W, B, Yf, nullptr, blockIdx.x);
}

// Both input feature transforms in one launch: blocks [0,gU) user, rest movie.
template<int KU, int KM>
__global__ void mp_transform_kernel(const float* __restrict__ Xu, int Nu,
                                    const float* __restrict__ Wu,
                                    const float* __restrict__ Bu,
                                    const float* __restrict__ Xm, int Nm,
                                    const float* __restrict__ Wm,
                                    const float* __restrict__ Bm,
                                    float* __restrict__ Y, int gU)
{
    if ((int)blockIdx.x < gU)
        mp_linear_body<KU, false, false>(Xu, Nu, Wu, Bu, Y, nullptr, blockIdx.x);
    else
        mp_linear_body<KM, false, false>(Xm, Nm, Wm, Bm,
                                         Y + (size_t)Nu * H_DIM, nullptr,
                                         blockIdx.x - gU);
}

// ---------------- aggregate: x[n] = relu(dinv[n]*(hs[n] + sum hs[src])) --------
// One warp per destination node; hs rows are fp16 (256 B), one uint2 (4 halfs)
// per lane per neighbor. Neighbor ids loaded cooperatively + shfl-broadcast.
__global__ void mp_aggregate_kernel(int N)
{
    int id = blockIdx.x * blockDim.x + threadIdx.x;
    int n = id >> 5;
    if (n >= N) return;
    int lane = id & 31;

    const uint2* hsp = reinterpret_cast<const uint2*>(g_hsh);

    uint2 u = __ldg(hsp + (size_t)n * 32 + lane);        // self-loop
    __half2 h0 = *reinterpret_cast<__half2*>(&u.x);
    __half2 h1 = *reinterpret_cast<__half2*>(&u.y);
    float2 f0 = __half22float2(h0);
    float2 f1 = __half22float2(h1);
    float4 acc = make_float4(f0.x, f0.y, f1.x, f1.y);

    int beg = g_off[n];
    int end = beg + g_deg[n];
    for (int base = beg; base < end; base += 32) {
        int m = end - base;
        if (m > 32) m = 32;
        int idx = (lane < m) ? g_csr[base + lane] : 0;
        #pragma unroll 4
        for (int j = 0; j < m; j++) {
            int r = __shfl_sync(0xffffffffu, idx, j);
            uint2 v = __ldg(hsp + (size_t)r * 32 + lane);
            __half2 a = *reinterpret_cast<__half2*>(&v.x);
            __half2 b = *reinterpret_cast<__half2*>(&v.y);
            float2 fa = __half22float2(a);
            float2 fb = __half22float2(b);
            acc.x += fa.x; acc.y += fa.y; acc.z += fb.x; acc.w += fb.y;
        }
    }

    float s = g_dinv[n];
    acc.x = fmaxf(acc.x * s, 0.f);
    acc.y = fmaxf(acc.y * s, 0.f);
    acc.z = fmaxf(acc.z * s, 0.f);
    acc.w = fmaxf(acc.w * s, 0.f);
    reinterpret_cast<float4*>(g_x)[(size_t)n * (H_DIM / 4) + lane] = acc;
}

// ---------------- node projection to C dims: pu = xu@WeU^T + be, pm = xm@WeM^T ----------------
__global__ void mp_proj_kernel(const float* __restrict__ We,
                               const float* __restrict__ be,
                               int Nu, int Nm, int C)
{
    __shared__ float WeS[MAX_C][2 * H_DIM];
    __shared__ float beS[MAX_C];
    int tid = threadIdx.x;
    for (int i = tid; i < C * 2 * H_DIM; i += blockDim.x)
        WeS[i / (2 * H_DIM)][i % (2 * H_DIM)] = We[i];
    if (tid < C) beS[tid] = be[tid];
    __syncthreads();

    int n = blockIdx.x * blockDim.x + tid;
    if (n >= Nu + Nm) return;
    bool isU = n < Nu;
    const float4* src = reinterpret_cast<const float4*>(g_x + (size_t)n * H_DIM);
    int wo = isU ? 0 : H_DIM;

    float acc[MAX_C];
    #pragma unroll
    for (int c = 0; c < MAX_C; c++) acc[c] = (c < C && isU) ? beS[c] : 0.f;

    #pragma unroll 4
    for (int q = 0; q < H_DIM / 4; q++) {
        float4 v = src[q];
        int k = q * 4 + wo;
        #pragma unroll
        for (int c = 0; c < MAX_C; c++) {
            if (c < C) {
                acc[c] += v.x * WeS[c][k + 0] + v.y * WeS[c][k + 1]
                        + v.z * WeS[c][k + 2] + v.w * WeS[c][k + 3];
            }
        }
    }

    float* dst = isU ? (g_pu + (size_t)n * PSTRIDE)
                     : (g_pm + (size_t)(n - Nu) * PSTRIDE);
    for (int c = 0; c < C; c++) dst[c] = acc[c];
}

// ---------------- out[e] = pu[row[e]] + pm[col[e]] ----------------
__global__ void mp_edge_out_kernel(float* __restrict__ out, int E, int C)
{
    int e = blockIdx.x * blockDim.x + threadIdx.x;
    if (e >= E) return;
    int r = g_row[e];
    int c = g_col[e];
    const float* a = g_pu + (size_t)r * PSTRIDE;
    const float* b = g_pm + (size_t)c * PSTRIDE;
    float* o = out + (size_t)e * C;
    if ((C & 1) == 0) {
        for (int k = 0; k < C; k += 2) {
            float2 av = *reinterpret_cast<const float2*>(a + k);
            float2 bv = *reinterpret_cast<const float2*>(b + k);
            float2 ov;
            ov.x = av.x + bv.x;
            ov.y = av.y + bv.y;
            *reinterpret_cast<float2*>(o + k) = ov;
        }
    } else {
        for (int k = 0; k < C; k++) o[k] = a[k] + b[k];
    }
}

// ---------------- host launch ----------------
extern "C" void kernel_launch(void* const* d_in, const int* in_sizes, int n_in,
                              void* d_out, int out_size)
{
    const float* x_user  = (const float*)d_in[0];
    const float* x_movie = (const float*)d_in[1];
    const void*  eidx    = d_in[2];
    const float* Wu = (const float*)d_in[3];
    const float* bu = (const float*)d_in[4];
    const float* Wm = (const float*)d_in[5];
    const float* bm = (const float*)d_in[6];
    const float* W1 = (const float*)d_in[7];
    const float* b1 = (const float*)d_in[8];
    const float* W2 = (const float*)d_in[9];
    const float* b2 = (const float*)d_in[10];
    const float* We = (const float*)d_in[11];
    const float* be = (const float*)d_in[12];
    float* out = (float*)d_out;

    const int H  = in_sizes[4];
    const int Fu = in_sizes[3] / H;
    const int Fm = in_sizes[5] / H;
    const int Nu = in_sizes[0] / Fu;
    const int Nm = in_sizes[1] / Fm;
    int E        = in_sizes[2] / 2;
    const int C  = in_sizes[12];
    const int Ntot = Nu + Nm;
    if (E > MAX_E) E = MAX_E;

    float*  xp;  cudaGetSymbolAddress((void**)&xp,  g_x);
    __half* hp;  cudaGetSymbolAddress((void**)&hp,  g_hsh);

    const int nb = (Ntot + SCAN_B - 1) / SCAN_B;

    mp_detect_zero_kernel<<<(Ntot + 255) / 256, 256>>>(eidx, Ntot);
    mp_convert_kernel<<<(E + 255) / 256, 256>>>(eidx, E);
    mp_scan1_kernel<<<nb, SCAN_B>>>(Ntot);
    mp_scan2_kernel<<<1, MAX_SCAN_BLK>>>(nb);
    mp_scan3_kernel<<<(Ntot + 255) / 256, 256>>>(Ntot);
    mp_fill_kernel<<<(E + 255) / 256, 256>>>(E);

    // Input feature transforms into g_x (single launch when shapes match)
    int gU = (Nu + TILE_N - 1) / TILE_N;
    int gM = (Nm + TILE_N - 1) / TILE_N;
    if (Fu == 32 && Fm == 64) {
        mp_transform_kernel<32, 64><<<gU + gM, 256>>>(
            x_user, Nu, Wu, bu, x_movie, Nm, Wm, bm, xp, gU);
    } else {
        if (Fu == 32)       mp_linear_f_kernel< 32><<<gU, 256>>>(x_user, Nu, Wu, bu, xp);
        else if (Fu == 64)  mp_linear_f_kernel< 64><<<gU, 256>>>(x_user, Nu, Wu, bu, xp);
        else                mp_linear_f_kernel<128><<<gU, 256>>>(x_user, Nu, Wu, bu, xp);
        float* dst = xp + (size_t)Nu * H_DIM;
        if (Fm == 32)       mp_linear_f_kernel< 32><<<gM, 256>>>(x_movie, Nm, Wm, bm, dst);
        else if (Fm == 64)  mp_linear_f_kernel< 64><<<gM, 256>>>(x_movie, Nm, Wm, bm, dst);
        else                mp_linear_f_kernel<128><<<gM, 256>>>(x_movie, Nm, Wm, bm, dst);
    }

    int gN = (Ntot + TILE_N - 1) / TILE_N;
    int gA = (int)(((long long)Ntot * 32 + 255) / 256);

    // GNN layer 1
    mp_linear_h_kernel<128><<<gN, 256>>>(xp, Ntot, W1, b1, hp);
    mp_aggregate_kernel<<<gA, 256>>>(Ntot);

    // GNN layer 2
    mp_linear_h_kernel<128><<<gN, 256>>>(xp, Ntot, W2, b2, hp);
    mp_aggregate_kernel<<<gA, 256>>>(Ntot);

    // Edge head: project nodes to C dims, then gather+add per edge
    mp_proj_kernel<<<(Ntot + 255) / 256, 256>>>(We, be, Nu, Nm, C);
    mp_edge_out_kernel<<<(E + 255) / 256, 256>>>(out, E, C);
}

// round 6
// speedup vs baseline: 1.5149x; 1.3805x over previous
#include <cuda_runtime.h>
#include <cuda_fp16.h>
#include <mma.h>
#include <cstdint>
#include <cstddef>

using namespace nvcuda;

#define H_DIM 128
#define TILE_N 64
#define BK 32
#define MAX_E 1048576
#define MAX_NODES 100480
#define MAX_SIDE 51200
#define PSTRIDE 12
#define MAX_C 12
#define SCAN_B 256
#define MAX_SCAN_BLK 512
#define STAGE_LD 132
#define SMEM_WMMA (128 * 128 * 2 + 8 * 16 * STAGE_LD * 4)

// ---------------- device scratch (no allocations allowed) ----------------
__device__ __align__(16) __half g_xh [(size_t)MAX_NODES * H_DIM];  // fp16 x
__device__ __align__(16) __half g_hsh[(size_t)MAX_NODES * H_DIM];  // fp16 hs
__device__ int   g_deg   [MAX_NODES];
__device__ int   g_off   [MAX_NODES];
__device__ int   g_cursor[MAX_NODES];
__device__ float g_dinv  [MAX_NODES];
__device__ int   g_row[MAX_E];
__device__ int   g_col[MAX_E];
__device__ int   g_csr[MAX_E];            // source node per bucketed edge
__device__ int   g_bsum [MAX_SCAN_BLK];
__device__ int   g_bsum2[MAX_SCAN_BLK];
__device__ float g_pu[(size_t)MAX_SIDE * PSTRIDE];
__device__ float g_pm[(size_t)MAX_SIDE * PSTRIDE];
__device__ int   g_is64;

// packed f32x2 FMA: d = a*b + d  (FFMA2 — only reachable via explicit PTX)
__device__ __forceinline__ void ffma2(unsigned long long& d,
                                      unsigned long long a,
                                      unsigned long long b)
{
    asm("fma.rn.f32x2 %0, %1, %2, %3;" : "=l"(d) : "l"(a), "l"(b), "l"(d));
}

// ---------------- detect edge dtype + zero degree array (fused) ----------------
__global__ void mp_detect_zero_kernel(const void* ei, int N)
{
    int i = blockIdx.x * blockDim.x + threadIdx.x;
    if (i < N) g_deg[i] = 0;
    if (i == 0) {
        const long long* p = (const long long*)ei;
        int is64 = 1;
        #pragma unroll 1
        for (int k = 0; k < 32; k++) {
            long long v = p[k];
            if (v < 0 || v >= (1LL << 32)) { is64 = 0; break; }
        }
        g_is64 = is64;
    }
}

// ---------------- convert edges to int32 + count in-degree (fused) ----------------
__global__ void mp_convert_kernel(const void* ei, int E)
{
    int e = blockIdx.x * blockDim.x + threadIdx.x;
    if (e >= E) return;
    int r, c;
    if (g_is64) {
        const long long* p = (const long long*)ei;
        r = (int)p[e];
        c = (int)p[(size_t)E + e];
    } else {
        const int* p = (const int*)ei;
        r = p[e];
        c = p[E + e];
    }
    g_row[e] = r;
    g_col[e] = c;
    atomicAdd(&g_deg[c], 1);
}

// ---------------- 3-phase exclusive scan over g_deg -> g_off ----------------
__global__ void mp_scan1_kernel(int N)
{
    __shared__ int sh[SCAN_B];
    int t = threadIdx.x;
    int i = blockIdx.x * SCAN_B + t;
    int v = (i < N) ? g_deg[i] : 0;
    sh[t] = v;
    __syncthreads();
    #pragma unroll
    for (int ofs = 1; ofs < SCAN_B; ofs <<= 1) {
        int u = (t >= ofs) ? sh[t - ofs] : 0;
        __syncthreads();
        sh[t] += u;
        __syncthreads();
    }
    if (i < N) g_off[i] = sh[t] - v;
    if (t == SCAN_B - 1) g_bsum[blockIdx.x] = sh[t];
}

__global__ void mp_scan2_kernel(int nb)
{
    __shared__ int sh[MAX_SCAN_BLK];
    int t = threadIdx.x;
    int v = (t < nb) ? g_bsum[t] : 0;
    sh[t] = v;
    __syncthreads();
    #pragma unroll
    for (int ofs = 1; ofs < MAX_SCAN_BLK; ofs <<= 1) {
        int u = (t >= ofs) ? sh[t - ofs] : 0;
        __syncthreads();
        sh[t] += u;
        __syncthreads();
    }
    if (t < nb) g_bsum2[t] = sh[t] - v;
}

__global__ void mp_scan3_kernel(int N)
{
    int i = blockIdx.x * blockDim.x + threadIdx.x;
    if (i >= N) return;
    int off = g_off[i] + g_bsum2[i >> 8];            // SCAN_B == 256
    g_off[i] = off;
    g_cursor[i] = off;
    g_dinv[i] = rsqrtf((float)(g_deg[i] + 1));
}

// ---------------- bucket fill: csr[pos] = row, bucketed by col ----------------
__global__ void mp_fill_kernel(int E)
{
    int e = blockIdx.x * blockDim.x + threadIdx.x;
    if (e >= E) return;
    int pos = atomicAdd(&g_cursor[g_col[e]], 1);
    g_csr[pos] = g_row[e];
}

// ---------------- input transforms: Yh = fp16(X @ W^T + b)  (FFMA2 path) --------
template<int K>
__device__ __forceinline__ void mp_linear_body(const float* __restrict__ X, int N,
                                               const float* __restrict__ W,
                                               const float* __restrict__ B,
                                               __half* __restrict__ Yh,
                                               int bid)
{
    __shared__ __align__(16) float  Ws[BK][H_DIM];      // transposed chunk [k][o]
    __shared__ __align__(16) float2 Xs[TILE_N][BK + 1]; // duplicated (v,v) pairs

    const int tid = threadIdx.x;
    const int tx = tid & 15;    // out-group (8 outs = 4 f32x2 pairs)
    const int ty = tid >> 4;    // node-group (4 nodes)
    const int node0 = bid * TILE_N;

    unsigned long long acc[4][4];
    #pragma unroll
    for (int i = 0; i < 4; i++)
        #pragma unroll
        for (int j = 0; j < 4; j++) acc[i][j] = 0ull;

    #pragma unroll 1
    for (int kc = 0; kc < K; kc += BK) {
        #pragma unroll
        for (int j = 0; j < (H_DIM * BK / 4) / 256; j++) {
            int f = tid + j * 256;
            int o = f >> 3;
            int q = f & 7;
            float4 v = *reinterpret_cast<const float4*>(W + (size_t)o * K + kc + q * 4);
            Ws[q * 4 + 0][o] = v.x;
            Ws[q * 4 + 1][o] = v.y;
            Ws[q * 4 + 2][o] = v.z;
            Ws[q * 4 + 3][o] = v.w;
        }
        #pragma unroll
        for (int j = 0; j < (TILE_N * BK / 4) / 256; j++) {
            int f = tid + j * 256;
            int n = f >> 3;
            int q = f & 7;
            int node = node0 + n;
            if (node >= N) node = N - 1;           // clamped (stores guarded)
            float4 v = *reinterpret_cast<const float4*>(X + (size_t)node * K + kc + q * 4);
            Xs[n][q * 4 + 0] = make_float2(v.x, v.x);
            Xs[n][q * 4 + 1] = make_float2(v.y, v.y);
            Xs[n][q * 4 + 2] = make_float2(v.z, v.z);
            Xs[n][q * 4 + 3] = make_float2(v.w, v.w);
        }
        __syncthreads();

        #pragma unroll 8
        for (int kk = 0; kk < BK; kk++) {
            const unsigned long long* wp =
                reinterpret_cast<const unsigned long long*>(&Ws[kk][0]);
            unsigned long long w0 = wp[tx * 4 + 0];
            unsigned long long w1 = wp[tx * 4 + 1];
            unsigned long long w2 = wp[tx * 4 + 2];
            unsigned long long w3 = wp[tx * 4 + 3];
            #pragma unroll
            for (int i = 0; i < 4; i++) {
                unsigned long long xv =
                    *reinterpret_cast<const unsigned long long*>(&Xs[ty * 4 + i][kk]);
                ffma2(acc[i][0], xv, w0);
                ffma2(acc[i][1], xv, w1);
                ffma2(acc[i][2], xv, w2);
                ffma2(acc[i][3], xv, w3);
            }
        }
        __syncthreads();
    }

    float breg[8];
    #pragma unroll
    for (int j = 0; j < 8; j++) breg[j] = B[tx * 8 + j];

    #pragma unroll
    for (int i = 0; i < 4; i++) {
        int node = node0 + ty * 4 + i;
        if (node >= N) continue;
        __half2 h[4];
        #pragma unroll
        for (int j = 0; j < 4; j++) {
            float2 p = *reinterpret_cast<float2*>(&acc[i][j]);
            h[j] = __floats2half2_rn(p.x + breg[2 * j], p.y + breg[2 * j + 1]);
        }
        *reinterpret_cast<uint4*>(Yh + (size_t)node * H_DIM + tx * 8) =
            *reinterpret_cast<const uint4*>(h);
    }
}

template<int K>
__global__ void mp_linear_kernel(const float* __restrict__ X, int N,
                                 const float* __restrict__ W,
                                 const float* __restrict__ B,
                                 __half* __restrict__ Yh)
{
    mp_linear_body<K>(X, N, W, B, Yh, blockIdx.x);
}

// Both input feature transforms in one launch: blocks [0,gU) user, rest movie.
template<int KU, int KM>
__global__ void mp_transform_kernel(const float* __restrict__ Xu, int Nu,
                                    const float* __restrict__ Wu,
                                    const float* __restrict__ Bu,
                                    const float* __restrict__ Xm, int Nm,
                                    const float* __restrict__ Wm,
                                    const float* __restrict__ Bm,
                                    __half* __restrict__ Y, int gU)
{
    if ((int)blockIdx.x < gU)
        mp_linear_body<KU>(Xu, Nu, Wu, Bu, Y, blockIdx.x);
    else
        mp_linear_body<KM>(Xm, Nm, Wm, Bm, Y + (size_t)Nu * H_DIM,
                           blockIdx.x - gU);
}

// ---------------- layer GEMM on tensor cores: hs = fp16(dinv*(xh @ W^T + b)) ----
// Block: 256 threads (8 warps), tile 128 nodes x 128 outs.  A = g_xh (fp16,
// row-major, global), B = W converted to fp16 in smem (row-major [o][k] read
// as col-major k x n frags).  fp32 accumulate, fused bias+dinv epilogue.
__global__ void mp_wmma_linear_kernel(const __half* __restrict__ A, int N,
                                      const float* __restrict__ W,
                                      const float* __restrict__ B,
                                      __half* __restrict__ Y)
{
    extern __shared__ __align__(16) char smem_raw[];
    __half* Wh    = reinterpret_cast<__half*>(smem_raw);             // 128x128
    float*  stage = reinterpret_cast<float*>(smem_raw + 128 * 128 * 2);

    const int tid  = threadIdx.x;
    const int w    = tid >> 5;
    const int lane = tid & 31;
    const int row0 = blockIdx.x * 128 + w * 16;

    // convert W (fp32 row-major) -> Wh (fp16 row-major) in smem
    for (int i = tid; i < 128 * 128 / 2; i += 256) {
        float2 v = reinterpret_cast<const float2*>(W)[i];
        reinterpret_cast<__half2*>(Wh)[i] = __floats2half2_rn(v.x, v.y);
    }
    __syncthreads();

    wmma::fragment<wmma::accumulator, 16, 16, 16, float> acc[8];
    #pragma unroll
    for (int n = 0; n < 8; n++) wmma::fill_fragment(acc[n], 0.f);

    #pragma unroll
    for (int k0 = 0; k0 < 8; k0++) {
        wmma::fragment<wmma::matrix_a, 16, 16, 16, __half, wmma::row_major> a;
        wmma::load_matrix_sync(a, A + (size_t)row0 * H_DIM + k0 * 16, H_DIM);
        #pragma unroll
        for (int n = 0; n < 8; n++) {
            wmma::fragment<wmma::matrix_b, 16, 16, 16, __half, wmma::col_major> b;
            // B(k,o) = W[o][k] -> col-major with ld = 128
            wmma::load_matrix_sync(b, Wh + n * 16 * 128 + k0 * 16, 128);
            wmma::mma_sync(acc[n], a, b, acc[n]);
        }
    }

    float* st = stage + w * 16 * STAGE_LD;
    #pragma unroll
    for (int n = 0; n < 8; n++)
        wmma::store_matrix_sync(st + n * 16, acc[n], STAGE_LD, wmma::mem_row_major);
    __syncwarp();

    // epilogue: each lane handles 8 (row, 8-col) chunks
    #pragma unroll
    for (int it = 0; it < 8; it++) {
        int idx = lane + it * 32;          // 0..255
        int r  = idx >> 4;                 // 0..15
        int c8 = (idx & 15) * 8;
        int node = row0 + r;
        if (node >= N) continue;
        float s = g_dinv[node];
        const float* sp = st + r * STAGE_LD + c8;
        __half2 h[4];
        #pragma unroll
        for (int j = 0; j < 4; j++) {
            float v0 = (sp[2 * j]     + B[c8 + 2 * j])     * s;
            float v1 = (sp[2 * j + 1] + B[c8 + 2 * j + 1]) * s;
            h[j] = __floats2half2_rn(v0, v1);
        }
        *reinterpret_cast<uint4*>(Y + (size_t)node * H_DIM + c8) =
            *reinterpret_cast<const uint4*>(h);
    }
}

// ---------------- aggregate: xh[n] = fp16(relu(dinv[n]*(hs[n] + sum hs[src]))) --
__global__ void mp_aggregate_kernel(int N)
{
    int id = blockIdx.x * blockDim.x + threadIdx.x;
    int n = id >> 5;
    if (n >= N) return;
    int lane = id & 31;

    const uint2* hsp = reinterpret_cast<const uint2*>(g_hsh);

    uint2 u = __ldg(hsp + (size_t)n * 32 + lane);        // self-loop
    __half2 h0 = *reinterpret_cast<__half2*>(&u.x);
    __half2 h1 = *reinterpret_cast<__half2*>(&u.y);
    float2 f0 = __half22float2(h0);
    float2 f1 = __half22float2(h1);
    float4 acc = make_float4(f0.x, f0.y, f1.x, f1.y);

    int beg = g_off[n];
    int end = beg + g_deg[n];
    for (int base = beg; base < end; base += 32) {
        int m = end - base;
        if (m > 32) m = 32;
        int idx = (lane < m) ? g_csr[base + lane] : 0;
        #pragma unroll 4
        for (int j = 0; j < m; j++) {
            int r = __shfl_sync(0xffffffffu, idx, j);
            uint2 v = __ldg(hsp + (size_t)r * 32 + lane);
            __half2 a = *reinterpret_cast<__half2*>(&v.x);
            __half2 b = *reinterpret_cast<__half2*>(&v.y);
            float2 fa = __half22float2(a);
            float2 fb = __half22float2(b);
            acc.x += fa.x; acc.y += fa.y; acc.z += fb.x; acc.w += fb.y;
        }
    }

    float s = g_dinv[n];
    __half2 o0 = __floats2half2_rn(fmaxf(acc.x * s, 0.f), fmaxf(acc.y * s, 0.f));
    __half2 o1 = __floats2half2_rn(fmaxf(acc.z * s, 0.f), fmaxf(acc.w * s, 0.f));
    uint2 ov;
    ov.x = *reinterpret_cast<uint32_t*>(&o0);
    ov.y = *reinterpret_cast<uint32_t*>(&o1);
    reinterpret_cast<uint2*>(g_xh)[(size_t)n * 32 + lane] = ov;
}

// ---------------- node projection to C dims (reads fp16 x) ----------------
__global__ void mp_proj_kernel(const float* __restrict__ We,
                               const float* __restrict__ be,
                               int Nu, int Nm, int C)
{
    __shared__ float WeS[MAX_C][2 * H_DIM];
    __shared__ float beS[MAX_C];
    int tid = threadIdx.x;
    for (int i = tid; i < C * 2 * H_DIM; i += blockDim.x)
        WeS[i / (2 * H_DIM)][i % (2 * H_DIM)] = We[i];
    if (tid < C) beS[tid] = be[tid];
    __syncthreads();

    int n = blockIdx.x * blockDim.x + tid;
    if (n >= Nu + Nm) return;
    bool isU = n < Nu;
    const uint2* src = reinterpret_cast<const uint2*>(g_xh + (size_t)n * H_DIM);
    int wo = isU ? 0 : H_DIM;

    float acc[MAX_C];
    #pragma unroll
    for (int c = 0; c < MAX_C; c++) acc[c] = (c < C && isU) ? beS[c] : 0.f;

    #pragma unroll 4
    for (int q = 0; q < H_DIM / 4; q++) {
        uint2 u = src[q];
        __half2 a = *reinterpret_cast<__half2*>(&u.x);
        __half2 b = *reinterpret_cast<__half2*>(&u.y);
        float2 fa = __half22float2(a);
        float2 fb = __half22float2(b);
        int k = q * 4 + wo;
        #pragma unroll
        for (int c = 0; c < MAX_C; c++) {
            if (c < C) {
                acc[c] += fa.x * WeS[c][k + 0] + fa.y * WeS[c][k + 1]
                        + fb.x * WeS[c][k + 2] + fb.y * WeS[c][k + 3];
            }
        }
    }

    float* dst = isU ? (g_pu + (size_t)n * PSTRIDE)
                     : (g_pm + (size_t)(n - Nu) * PSTRIDE);
    for (int c = 0; c < C; c++) dst[c] = acc[c];
}

// ---------------- out[e] = pu[row[e]] + pm[col[e]] ----------------
__global__ void mp_edge_out_kernel(float* __restrict__ out, int E, int C)
{
    int e = blockIdx.x * blockDim.x + threadIdx.x;
    if (e >= E) return;
    int r = g_row[e];
    int c = g_col[e];
    const float* a = g_pu + (size_t)r * PSTRIDE;
    const float* b = g_pm + (size_t)c * PSTRIDE;
    float* o = out + (size_t)e * C;
    if ((C & 1) == 0) {
        for (int k = 0; k < C; k += 2) {
            float2 av = *reinterpret_cast<const float2*>(a + k);
            float2 bv = *reinterpret_cast<const float2*>(b + k);
            float2 ov;
            ov.x = av.x + bv.x;
            ov.y = av.y + bv.y;
            *reinterpret_cast<float2*>(o + k) = ov;
        }
    } else {
        for (int k = 0; k < C; k++) o[k] = a[k] + b[k];
    }
}

// ---------------- host launch ----------------
extern "C" void kernel_launch(void* const* d_in, const int* in_sizes, int n_in,
                              void* d_out, int out_size)
{
    const float* x_user  = (const float*)d_in[0];
    const float* x_movie = (const float*)d_in[1];
    const void*  eidx    = d_in[2];
    const float* Wu = (const float*)d_in[3];
    const float* bu = (const float*)d_in[4];
    const float* Wm = (const float*)d_in[5];
    const float* bm = (const float*)d_in[6];
    const float* W1 = (const float*)d_in[7];
    const float* b1 = (const float*)d_in[8];
    const float* W2 = (const float*)d_in[9];
    const float* b2 = (const float*)d_in[10];
    const float* We = (const float*)d_in[11];
    const float* be = (const float*)d_in[12];
    float* out = (float*)d_out;

    const int H  = in_sizes[4];
    const int Fu = in_sizes[3] / H;
    const int Fm = in_sizes[5] / H;
    const int Nu = in_sizes[0] / Fu;
    const int Nm = in_sizes[1] / Fm;
    int E        = in_sizes[2] / 2;
    const int C  = in_sizes[12];
    const int Ntot = Nu + Nm;
    if (E > MAX_E) E = MAX_E;

    __half* xhp; cudaGetSymbolAddress((void**)&xhp, g_xh);
    __half* hp;  cudaGetSymbolAddress((void**)&hp,  g_hsh);

    cudaFuncSetAttribute(mp_wmma_linear_kernel,
                         cudaFuncAttributeMaxDynamicSharedMemorySize, SMEM_WMMA);

    const int nb = (Ntot + SCAN_B - 1) / SCAN_B;

    mp_detect_zero_kernel<<<(Ntot + 255) / 256, 256>>>(eidx, Ntot);
    mp_convert_kernel<<<(E + 255) / 256, 256>>>(eidx, E);
    mp_scan1_kernel<<<nb, SCAN_B>>>(Ntot);
    mp_scan2_kernel<<<1, MAX_SCAN_BLK>>>(nb);
    mp_scan3_kernel<<<(Ntot + 255) / 256, 256>>>(Ntot);
    mp_fill_kernel<<<(E + 255) / 256, 256>>>(E);

    // Input feature transforms into g_xh (single launch when shapes match)
    int gU = (Nu + TILE_N - 1) / TILE_N;
    int gM = (Nm + TILE_N - 1) / TILE_N;
    if (Fu == 32 && Fm == 64) {
        mp_transform_kernel<32, 64><<<gU + gM, 256>>>(
            x_user, Nu, Wu, bu, x_movie, Nm, Wm, bm, xhp, gU);
    } else {
        if (Fu == 32)       mp_linear_kernel< 32><<<gU, 256>>>(x_user, Nu, Wu, bu, xhp);
        else if (Fu == 64)  mp_linear_kernel< 64><<<gU, 256>>>(x_user, Nu, Wu, bu, xhp);
        else                mp_linear_kernel<128><<<gU, 256>>>(x_user, Nu, Wu, bu, xhp);
        __half* dst = xhp + (size_t)Nu * H_DIM;
        if (Fm == 32)       mp_linear_kernel< 32><<<gM, 256>>>(x_movie, Nm, Wm, bm, dst);
        else if (Fm == 64)  mp_linear_kernel< 64><<<gM, 256>>>(x_movie, Nm, Wm, bm, dst);
        else                mp_linear_kernel<128><<<gM, 256>>>(x_movie, Nm, Wm, bm, dst);
    }

    int gW = (Ntot + 127) / 128;
    int gA = (int)(((long long)Ntot * 32 + 255) / 256);

    // GNN layer 1 (tensor-core GEMM)
    mp_wmma_linear_kernel<<<gW, 256, SMEM_WMMA>>>(xhp, Ntot, W1, b1, hp);
    mp_aggregate_kernel<<<gA, 256>>>(Ntot);

    // GNN layer 2
    mp_wmma_linear_kernel<<<gW, 256, SMEM_WMMA>>>(xhp, Ntot, W2, b2, hp);
    mp_aggregate_kernel<<<gA, 256>>>(Ntot);

    // Edge head: project nodes to C dims, then gather+add per edge
    mp_proj_kernel<<<(Ntot + 255) / 256, 256>>>(We, be, Nu, Nm, C);
    mp_edge_out_kernel<<<(E + 255) / 256, 256>>>(out, E, C);
}